// round 1
// baseline (speedup 1.0000x reference)
#include <cuda_runtime.h>
#include <math.h>

#define TILE      64
#define NTHREADS  256
#define ED        64

// ---- shared memory layout (in floats) ----
#define OFF_NW1   0                   // 64x64
#define OFF_NW2   4096                // 64x64
#define OFF_AW1   8192                // 128x64
#define OFF_AW2   16384               // 64x64
#define OFF_OW1   20480               // 128x64
#define OFF_OW2   28672               // 64x64
#define OFF_NB1   32768
#define OFF_NB2   (32768+64)
#define OFF_AB1   (32768+128)
#define OFF_AB2   (32768+192)
#define OFF_OB1   (32768+256)
#define OFF_OB2   (32768+320)
#define OFF_TV    (32768+384)
#define OFF_ACT   (32768+448)         // 4 buffers of 64x64 floats ([feature][sample])
#define SMEM_FLOATS (OFF_ACT + 4*4096)   // 49600 floats = 198400 bytes

// cooperative vectorized copy gmem -> smem
__device__ __forceinline__ void cpv(float* dst, const float* src, int n4, int tid) {
    const float4* s4 = (const float4*)src;
    float4* d4 = (float4*)dst;
    for (int i = tid; i < n4; i += NTHREADS) d4[i] = s4[i];
}

// gather 64 embedding rows into activation buffer, layout dst[k][s] (k-major)
__device__ __forceinline__ void gather_rows(
    float* __restrict__ dst, const float* __restrict__ item,
    const int* __restrict__ idx, int stride, int off, int gs0, int tid)
{
    int s    = tid >> 2;        // 64 samples, 4 threads each
    int part = tid & 3;         // each thread: 4 float4 chunks
    int row  = idx[(gs0 + s) * stride + off];
    const float4* src = (const float4*)(item + (size_t)row * ED);
#pragma unroll
    for (int i = 0; i < 4; i++) {
        int c = (part << 2) + i;       // float4 chunk index 0..15
        float4 v = src[c];
        int k = c * 4;
        dst[(k + 0) * 64 + s] = v.x;
        dst[(k + 1) * 64 + s] = v.y;
        dst[(k + 2) * 64 + s] = v.z;
        dst[(k + 3) * 64 + s] = v.w;
    }
}

// One dense layer over the 64-sample tile:
//   OUT[j][s] = act( b[j] + sum_k A0[k][s]*W[k][j]  (+ sum_k A1[k][s]*W[64+k][j]) )
// A*, OUT are [64][64] feature-major in smem; W is [K][64] row-major in smem.
// Each thread computes a 4(sample) x 4(col) register tile.
__device__ __forceinline__ void mlp_layer(
    const float* __restrict__ A0, const float* __restrict__ A1,
    const float* __restrict__ W,  const float* __restrict__ b,
    float* __restrict__ OUT, bool lrelu, int tid)
{
    const int tx = tid & 15;    // sample quad
    const int ty = tid >> 4;    // col quad
    const int s0 = tx * 4, j0 = ty * 4;

    float acc[4][4];
#pragma unroll
    for (int jj = 0; jj < 4; jj++) {
        float bv = b[j0 + jj];
        acc[0][jj] = bv; acc[1][jj] = bv; acc[2][jj] = bv; acc[3][jj] = bv;
    }

#pragma unroll 4
    for (int k = 0; k < 64; k++) {
        float4 a = *(const float4*)(A0 + k * 64 + s0);
        float4 w = *(const float4*)(W  + k * 64 + j0);
        acc[0][0] += a.x * w.x; acc[0][1] += a.x * w.y; acc[0][2] += a.x * w.z; acc[0][3] += a.x * w.w;
        acc[1][0] += a.y * w.x; acc[1][1] += a.y * w.y; acc[1][2] += a.y * w.z; acc[1][3] += a.y * w.w;
        acc[2][0] += a.z * w.x; acc[2][1] += a.z * w.y; acc[2][2] += a.z * w.z; acc[2][3] += a.z * w.w;
        acc[3][0] += a.w * w.x; acc[3][1] += a.w * w.y; acc[3][2] += a.w * w.z; acc[3][3] += a.w * w.w;
    }
    if (A1) {
        const float* W2 = W + 64 * 64;
#pragma unroll 4
        for (int k = 0; k < 64; k++) {
            float4 a = *(const float4*)(A1 + k * 64 + s0);
            float4 w = *(const float4*)(W2 + k * 64 + j0);
            acc[0][0] += a.x * w.x; acc[0][1] += a.x * w.y; acc[0][2] += a.x * w.z; acc[0][3] += a.x * w.w;
            acc[1][0] += a.y * w.x; acc[1][1] += a.y * w.y; acc[1][2] += a.y * w.z; acc[1][3] += a.y * w.w;
            acc[2][0] += a.z * w.x; acc[2][1] += a.z * w.y; acc[2][2] += a.z * w.z; acc[2][3] += a.z * w.w;
            acc[3][0] += a.w * w.x; acc[3][1] += a.w * w.y; acc[3][2] += a.w * w.z; acc[3][3] += a.w * w.w;
        }
    }

#pragma unroll
    for (int jj = 0; jj < 4; jj++) {
        float4 v = make_float4(acc[0][jj], acc[1][jj], acc[2][jj], acc[3][jj]);
        if (lrelu) {
            v.x = v.x > 0.f ? v.x : 0.01f * v.x;
            v.y = v.y > 0.f ? v.y : 0.01f * v.y;
            v.z = v.z > 0.f ? v.z : 0.01f * v.z;
            v.w = v.w > 0.f ? v.w : 0.01f * v.w;
        }
        *(float4*)(OUT + (j0 + jj) * 64 + s0) = v;
    }
}

// cosine-similarity epilogue for one 64-sample tile
__device__ __forceinline__ void epilogue(
    const float* __restrict__ P, const float* __restrict__ tv,
    float tnorm, float* __restrict__ out, int tid)
{
    if (tid < 64) {
        int s = tid;
        float num = 0.f, nn = 0.f;
#pragma unroll 8
        for (int j = 0; j < 64; j++) {
            float v = P[j * 64 + s];
            num = fmaf(v, tv[j], num);
            nn  = fmaf(v, v, nn);
        }
        float en = fmaxf(sqrtf(nn), 1e-8f);
        float d  = en * fmaxf(tnorm, 1e-8f);
        out[s] = num / d * 10.0f;
    }
}

__global__ void __launch_bounds__(NTHREADS, 1)
logicnet_kernel(
    const int*   __restrict__ seq,       // [B,5]
    const int*   __restrict__ pos_t,     // [B]
    const int*   __restrict__ neg_t,     // [B]
    const float* __restrict__ item,      // [1e6,64]
    const float* __restrict__ tvec,      // [64]
    const float* __restrict__ nW1, const float* __restrict__ nb1,
    const float* __restrict__ nW2, const float* __restrict__ nb2,
    const float* __restrict__ aW1, const float* __restrict__ ab1,
    const float* __restrict__ aW2, const float* __restrict__ ab2,
    const float* __restrict__ oW1, const float* __restrict__ ob1,
    const float* __restrict__ oW2, const float* __restrict__ ob2,
    float* __restrict__ out, int batch)
{
    extern __shared__ float sm[];
    const int tid = threadIdx.x;
    const int gs0 = blockIdx.x * TILE;

    float* B0 = sm + OFF_ACT;
    float* B1 = sm + OFF_ACT + 4096;
    float* B2 = sm + OFF_ACT + 8192;
    float* B3 = sm + OFF_ACT + 12288;

    // stage weights/biases/true_vec; overlap first two gathers with weight load
    cpv(sm + OFF_NW1, nW1, 1024, tid);
    cpv(sm + OFF_NW2, nW2, 1024, tid);
    cpv(sm + OFF_AW1, aW1, 2048, tid);
    cpv(sm + OFF_AW2, aW2, 1024, tid);
    cpv(sm + OFF_OW1, oW1, 2048, tid);
    cpv(sm + OFF_OW2, oW2, 1024, tid);
    cpv(sm + OFF_NB1, nb1, 16, tid);
    cpv(sm + OFF_NB2, nb2, 16, tid);
    cpv(sm + OFF_AB1, ab1, 16, tid);
    cpv(sm + OFF_AB2, ab2, 16, tid);
    cpv(sm + OFF_OB1, ob1, 16, tid);
    cpv(sm + OFF_OB2, ob2, 16, tid);
    cpv(sm + OFF_TV,  tvec, 16, tid);
    gather_rows(B0, item, seq, 5, 0, gs0, tid);   // e0
    gather_rows(B1, item, seq, 5, 1, gs0, tid);   // e1
    __syncthreads();

    const float* tv = sm + OFF_TV;
    float tn2 = 0.f;
#pragma unroll 8
    for (int j = 0; j < 64; j++) tn2 = fmaf(tv[j], tv[j], tn2);
    float tnorm = sqrtf(tn2);

    const float* snW1 = sm + OFF_NW1; const float* snW2 = sm + OFF_NW2;
    const float* saW1 = sm + OFF_AW1; const float* saW2 = sm + OFF_AW2;
    const float* soW1 = sm + OFF_OW1; const float* soW2 = sm + OFF_OW2;
    const float* snb1 = sm + OFF_NB1; const float* snb2 = sm + OFF_NB2;
    const float* sab1 = sm + OFF_AB1; const float* sab2 = sm + OFF_AB2;
    const float* sob1 = sm + OFF_OB1; const float* sob2 = sm + OFF_OB2;

    // n1 = NOT(e1)
    mlp_layer(B1, 0, snW1, snb1, B2, true,  tid); __syncthreads();
    mlp_layer(B2, 0, snW2, snb2, B1, false, tid); __syncthreads();
    // i5 = AND(e0 || n1)  -> B0
    mlp_layer(B0, B1, saW1, sab1, B2, true,  tid); __syncthreads();
    mlp_layer(B2, 0,  saW2, sab2, B0, false, tid);
    // gather e2, e3
    __syncthreads();
    gather_rows(B1, item, seq, 5, 2, gs0, tid);   // e2
    gather_rows(B3, item, seq, 5, 3, gs0, tid);   // e3
    __syncthreads();
    // i6 = OR(e2 || e3) -> B1
    mlp_layer(B1, B3, soW1, sob1, B2, true,  tid); __syncthreads();
    mlp_layer(B2, 0,  soW2, sob2, B1, false, tid); __syncthreads();
    // i7 = AND(i5 || i6) -> B0
    mlp_layer(B0, B1, saW1, sab1, B2, true,  tid); __syncthreads();
    mlp_layer(B2, 0,  saW2, sab2, B0, false, tid); __syncthreads();
    // n7 = NOT(i7) -> B1 ; gather e4 -> B3
    mlp_layer(B0, 0, snW1, snb1, B2, true,  tid); __syncthreads();
    mlp_layer(B2, 0, snW2, snb2, B1, false, tid);
    gather_rows(B3, item, seq, 5, 4, gs0, tid);   // e4
    __syncthreads();
    // out = OR(n7 || e4) -> B0
    mlp_layer(B1, B3, soW1, sob1, B2, true,  tid); __syncthreads();
    mlp_layer(B2, 0,  soW2, sob2, B0, false, tid); __syncthreads();
    // enc_not = NOT(out) -> B1 ; gather pos_e -> B3
    mlp_layer(B0, 0, snW1, snb1, B2, true,  tid); __syncthreads();
    mlp_layer(B2, 0, snW2, snb2, B1, false, tid);
    gather_rows(B3, item, pos_t, 1, 0, gs0, tid); // pos_e
    __syncthreads();
    // encoded_pos = OR(enc_not || pos_e) -> B0
    mlp_layer(B1, B3, soW1, sob1, B2, true,  tid); __syncthreads();
    mlp_layer(B2, 0,  soW2, sob2, B0, false, tid); __syncthreads();
    epilogue(B0, tv, tnorm, out + gs0, tid);
    // gather neg_e -> B3 (B3 free; epilogue only reads B0)
    gather_rows(B3, item, neg_t, 1, 0, gs0, tid);
    __syncthreads();
    // encoded_neg = OR(enc_not || neg_e) -> B0
    mlp_layer(B1, B3, soW1, sob1, B2, true,  tid); __syncthreads();
    mlp_layer(B2, 0,  soW2, sob2, B0, false, tid); __syncthreads();
    epilogue(B0, tv, tnorm, out + batch + gs0, tid);
}

extern "C" void kernel_launch(void* const* d_in, const int* in_sizes, int n_in,
                              void* d_out, int out_size) {
    const int*   seq   = (const int*)  d_in[0];
    const int*   pos_t = (const int*)  d_in[1];
    const int*   neg_t = (const int*)  d_in[2];
    const float* item  = (const float*)d_in[3];
    const float* tvec  = (const float*)d_in[4];
    const float* nW1 = (const float*)d_in[5];
    const float* nb1 = (const float*)d_in[6];
    const float* nW2 = (const float*)d_in[7];
    const float* nb2 = (const float*)d_in[8];
    const float* aW1 = (const float*)d_in[9];
    const float* ab1 = (const float*)d_in[10];
    const float* aW2 = (const float*)d_in[11];
    const float* ab2 = (const float*)d_in[12];
    const float* oW1 = (const float*)d_in[13];
    const float* ob1 = (const float*)d_in[14];
    const float* oW2 = (const float*)d_in[15];
    const float* ob2 = (const float*)d_in[16];
    float* out = (float*)d_out;

    int batch = in_sizes[1];             // pos_target element count
    int grid  = batch / TILE;
    size_t smem = SMEM_FLOATS * sizeof(float);

    cudaFuncSetAttribute(logicnet_kernel,
                         cudaFuncAttributeMaxDynamicSharedMemorySize, (int)smem);

    logicnet_kernel<<<grid, NTHREADS, smem>>>(
        seq, pos_t, neg_t, item, tvec,
        nW1, nb1, nW2, nb2, aW1, ab1, aW2, ab2, oW1, ob1, oW2, ob2,
        out, batch);
}

// round 2
// speedup vs baseline: 1.0511x; 1.0511x over previous
#include <cuda_runtime.h>
#include <math.h>

#define TILE      64
#define NTHREADS  256
#define ED        64

// ---- shared memory layout (in floats) ----
#define OFF_NW1   0                   // 64x64
#define OFF_NW2   4096                // 64x64
#define OFF_AW1   8192                // 128x64
#define OFF_AW2   16384               // 64x64
#define OFF_OW1   20480               // 128x64
#define OFF_OW2   28672               // 64x64
#define OFF_NB1   32768
#define OFF_NB2   (32768+64)
#define OFF_AB1   (32768+128)
#define OFF_AB2   (32768+192)
#define OFF_OB1   (32768+256)
#define OFF_OB2   (32768+320)
#define OFF_TV    (32768+384)
#define OFF_ACT   (32768+448)         // 4 buffers of 64x64 floats ([feature][sample])
#define SMEM_FLOATS (OFF_ACT + 4*4096)   // 49600 floats = 198400 bytes

// cooperative vectorized copy gmem -> smem
__device__ __forceinline__ void cpv(float* dst, const float* src, int n4, int tid) {
    const float4* s4 = (const float4*)src;
    float4* d4 = (float4*)dst;
    for (int i = tid; i < n4; i += NTHREADS) d4[i] = s4[i];
}

// gather 64 embedding rows into activation buffer, layout dst[k][s] (k-major)
__device__ __forceinline__ void gather_rows(
    float* __restrict__ dst, const float* __restrict__ item,
    const int* __restrict__ idx, int stride, int off, int gs0, int tid)
{
    int s    = tid >> 2;        // 64 samples, 4 threads each
    int part = tid & 3;         // each thread: 4 float4 chunks
    int row  = idx[(gs0 + s) * stride + off];
    const float4* src = (const float4*)(item + (size_t)row * ED);
#pragma unroll
    for (int i = 0; i < 4; i++) {
        int c = (part << 2) + i;       // float4 chunk index 0..15
        float4 v = src[c];
        int k = c * 4;
        dst[(k + 0) * 64 + s] = v.x;
        dst[(k + 1) * 64 + s] = v.y;
        dst[(k + 2) * 64 + s] = v.z;
        dst[(k + 3) * 64 + s] = v.w;
    }
}

// One dense layer over the 64-sample tile:
//   OUT[j][s] = act( b[j] + sum_k A0[k][s]*W[k][j]  (+ sum_k A1[k][s]*W[64+k][j]) )
// A*, OUT are [64][64] feature-major in smem; W is [K][64] row-major in smem.
// Each thread computes a 4(sample) x 4(col) register tile.
__device__ __forceinline__ void mlp_layer(
    const float* __restrict__ A0, const float* __restrict__ A1,
    const float* __restrict__ W,  const float* __restrict__ b,
    float* __restrict__ OUT, bool lrelu, int tid)
{
    const int tx = tid & 15;    // sample quad
    const int ty = tid >> 4;    // col quad
    const int s0 = tx * 4, j0 = ty * 4;

    float acc[4][4];
#pragma unroll
    for (int jj = 0; jj < 4; jj++) {
        float bv = b[j0 + jj];
        acc[0][jj] = bv; acc[1][jj] = bv; acc[2][jj] = bv; acc[3][jj] = bv;
    }

#pragma unroll 4
    for (int k = 0; k < 64; k++) {
        float4 a = *(const float4*)(A0 + k * 64 + s0);
        float4 w = *(const float4*)(W  + k * 64 + j0);
        acc[0][0] += a.x * w.x; acc[0][1] += a.x * w.y; acc[0][2] += a.x * w.z; acc[0][3] += a.x * w.w;
        acc[1][0] += a.y * w.x; acc[1][1] += a.y * w.y; acc[1][2] += a.y * w.z; acc[1][3] += a.y * w.w;
        acc[2][0] += a.z * w.x; acc[2][1] += a.z * w.y; acc[2][2] += a.z * w.z; acc[2][3] += a.z * w.w;
        acc[3][0] += a.w * w.x; acc[3][1] += a.w * w.y; acc[3][2] += a.w * w.z; acc[3][3] += a.w * w.w;
    }
    if (A1) {
        const float* W2 = W + 64 * 64;
#pragma unroll 4
        for (int k = 0; k < 64; k++) {
            float4 a = *(const float4*)(A1 + k * 64 + s0);
            float4 w = *(const float4*)(W2 + k * 64 + j0);
            acc[0][0] += a.x * w.x; acc[0][1] += a.x * w.y; acc[0][2] += a.x * w.z; acc[0][3] += a.x * w.w;
            acc[1][0] += a.y * w.x; acc[1][1] += a.y * w.y; acc[1][2] += a.y * w.z; acc[1][3] += a.y * w.w;
            acc[2][0] += a.z * w.x; acc[2][1] += a.z * w.y; acc[2][2] += a.z * w.z; acc[2][3] += a.z * w.w;
            acc[3][0] += a.w * w.x; acc[3][1] += a.w * w.y; acc[3][2] += a.w * w.z; acc[3][3] += a.w * w.w;
        }
    }

#pragma unroll
    for (int jj = 0; jj < 4; jj++) {
        float4 v = make_float4(acc[0][jj], acc[1][jj], acc[2][jj], acc[3][jj]);
        if (lrelu) {
            v.x = v.x > 0.f ? v.x : 0.01f * v.x;
            v.y = v.y > 0.f ? v.y : 0.01f * v.y;
            v.z = v.z > 0.f ? v.z : 0.01f * v.z;
            v.w = v.w > 0.f ? v.w : 0.01f * v.w;
        }
        *(float4*)(OUT + (j0 + jj) * 64 + s0) = v;
    }
}

// cosine-similarity epilogue for one 64-sample tile
__device__ __forceinline__ void epilogue(
    const float* __restrict__ P, const float* __restrict__ tv,
    float tnorm, float* __restrict__ out, int tid)
{
    if (tid < 64) {
        int s = tid;
        float num = 0.f, nn = 0.f;
#pragma unroll 8
        for (int j = 0; j < 64; j++) {
            float v = P[j * 64 + s];
            num = fmaf(v, tv[j], num);
            nn  = fmaf(v, v, nn);
        }
        float en = fmaxf(sqrtf(nn), 1e-8f);
        float d  = en * fmaxf(tnorm, 1e-8f);
        out[s] = num / d * 10.0f;
    }
}

__global__ void __launch_bounds__(NTHREADS, 1)
logicnet_kernel(
    const int*   __restrict__ seq,       // [B,5]
    const int*   __restrict__ pos_t,     // [B]
    const int*   __restrict__ neg_t,     // [B]
    const float* __restrict__ item,      // [1e6,64]
    const float* __restrict__ tvec,      // [64]
    const float* __restrict__ nW1, const float* __restrict__ nb1,
    const float* __restrict__ nW2, const float* __restrict__ nb2,
    const float* __restrict__ aW1, const float* __restrict__ ab1,
    const float* __restrict__ aW2, const float* __restrict__ ab2,
    const float* __restrict__ oW1, const float* __restrict__ ob1,
    const float* __restrict__ oW2, const float* __restrict__ ob2,
    float* __restrict__ out, int batch)
{
    extern __shared__ float sm[];
    const int tid = threadIdx.x;
    const int gs0 = blockIdx.x * TILE;

    float* B0 = sm + OFF_ACT;
    float* B1 = sm + OFF_ACT + 4096;
    float* B2 = sm + OFF_ACT + 8192;
    float* B3 = sm + OFF_ACT + 12288;

    // stage weights/biases/true_vec; overlap first two gathers with weight load
    cpv(sm + OFF_NW1, nW1, 1024, tid);
    cpv(sm + OFF_NW2, nW2, 1024, tid);
    cpv(sm + OFF_AW1, aW1, 2048, tid);
    cpv(sm + OFF_AW2, aW2, 1024, tid);
    cpv(sm + OFF_OW1, oW1, 2048, tid);
    cpv(sm + OFF_OW2, oW2, 1024, tid);
    cpv(sm + OFF_NB1, nb1, 16, tid);
    cpv(sm + OFF_NB2, nb2, 16, tid);
    cpv(sm + OFF_AB1, ab1, 16, tid);
    cpv(sm + OFF_AB2, ab2, 16, tid);
    cpv(sm + OFF_OB1, ob1, 16, tid);
    cpv(sm + OFF_OB2, ob2, 16, tid);
    cpv(sm + OFF_TV,  tvec, 16, tid);
    gather_rows(B0, item, seq, 5, 0, gs0, tid);   // e0
    gather_rows(B1, item, seq, 5, 1, gs0, tid);   // e1
    __syncthreads();

    const float* tv = sm + OFF_TV;
    float tn2 = 0.f;
#pragma unroll 8
    for (int j = 0; j < 64; j++) tn2 = fmaf(tv[j], tv[j], tn2);
    float tnorm = sqrtf(tn2);

    const float* snW1 = sm + OFF_NW1; const float* snW2 = sm + OFF_NW2;
    const float* saW1 = sm + OFF_AW1; const float* saW2 = sm + OFF_AW2;
    const float* soW1 = sm + OFF_OW1; const float* soW2 = sm + OFF_OW2;
    const float* snb1 = sm + OFF_NB1; const float* snb2 = sm + OFF_NB2;
    const float* sab1 = sm + OFF_AB1; const float* sab2 = sm + OFF_AB2;
    const float* sob1 = sm + OFF_OB1; const float* sob2 = sm + OFF_OB2;

    // n1 = NOT(e1)
    mlp_layer(B1, 0, snW1, snb1, B2, true,  tid); __syncthreads();
    mlp_layer(B2, 0, snW2, snb2, B1, false, tid); __syncthreads();
    // i5 = AND(e0 || n1)  -> B0
    mlp_layer(B0, B1, saW1, sab1, B2, true,  tid); __syncthreads();
    mlp_layer(B2, 0,  saW2, sab2, B0, false, tid);
    // gather e2, e3
    __syncthreads();
    gather_rows(B1, item, seq, 5, 2, gs0, tid);   // e2
    gather_rows(B3, item, seq, 5, 3, gs0, tid);   // e3
    __syncthreads();
    // i6 = OR(e2 || e3) -> B1
    mlp_layer(B1, B3, soW1, sob1, B2, true,  tid); __syncthreads();
    mlp_layer(B2, 0,  soW2, sob2, B1, false, tid); __syncthreads();
    // i7 = AND(i5 || i6) -> B0
    mlp_layer(B0, B1, saW1, sab1, B2, true,  tid); __syncthreads();
    mlp_layer(B2, 0,  saW2, sab2, B0, false, tid); __syncthreads();
    // n7 = NOT(i7) -> B1 ; gather e4 -> B3
    mlp_layer(B0, 0, snW1, snb1, B2, true,  tid); __syncthreads();
    mlp_layer(B2, 0, snW2, snb2, B1, false, tid);
    gather_rows(B3, item, seq, 5, 4, gs0, tid);   // e4
    __syncthreads();
    // out = OR(n7 || e4) -> B0
    mlp_layer(B1, B3, soW1, sob1, B2, true,  tid); __syncthreads();
    mlp_layer(B2, 0,  soW2, sob2, B0, false, tid); __syncthreads();
    // enc_not = NOT(out) -> B1 ; gather pos_e -> B3
    mlp_layer(B0, 0, snW1, snb1, B2, true,  tid); __syncthreads();
    mlp_layer(B2, 0, snW2, snb2, B1, false, tid);
    gather_rows(B3, item, pos_t, 1, 0, gs0, tid); // pos_e
    __syncthreads();
    // encoded_pos = OR(enc_not || pos_e) -> B0
    mlp_layer(B1, B3, soW1, sob1, B2, true,  tid); __syncthreads();
    mlp_layer(B2, 0,  soW2, sob2, B0, false, tid); __syncthreads();
    epilogue(B0, tv, tnorm, out + gs0, tid);
    // gather neg_e -> B3 (B3 free; epilogue only reads B0)
    gather_rows(B3, item, neg_t, 1, 0, gs0, tid);
    __syncthreads();
    // encoded_neg = OR(enc_not || neg_e) -> B0
    mlp_layer(B1, B3, soW1, sob1, B2, true,  tid); __syncthreads();
    mlp_layer(B2, 0,  soW2, sob2, B0, false, tid); __syncthreads();
    epilogue(B0, tv, tnorm, out + batch + gs0, tid);
}

extern "C" void kernel_launch(void* const* d_in, const int* in_sizes, int n_in,
                              void* d_out, int out_size) {
    const int*   seq   = (const int*)  d_in[0];
    const int*   pos_t = (const int*)  d_in[1];
    const int*   neg_t = (const int*)  d_in[2];
    const float* item  = (const float*)d_in[3];
    const float* tvec  = (const float*)d_in[4];
    const float* nW1 = (const float*)d_in[5];
    const float* nb1 = (const float*)d_in[6];
    const float* nW2 = (const float*)d_in[7];
    const float* nb2 = (const float*)d_in[8];
    const float* aW1 = (const float*)d_in[9];
    const float* ab1 = (const float*)d_in[10];
    const float* aW2 = (const float*)d_in[11];
    const float* ab2 = (const float*)d_in[12];
    const float* oW1 = (const float*)d_in[13];
    const float* ob1 = (const float*)d_in[14];
    const float* oW2 = (const float*)d_in[15];
    const float* ob2 = (const float*)d_in[16];
    float* out = (float*)d_out;

    int batch = in_sizes[1];             // pos_target element count
    int grid  = batch / TILE;
    size_t smem = SMEM_FLOATS * sizeof(float);

    cudaFuncSetAttribute(logicnet_kernel,
                         cudaFuncAttributeMaxDynamicSharedMemorySize, (int)smem);

    logicnet_kernel<<<grid, NTHREADS, smem>>>(
        seq, pos_t, neg_t, item, tvec,
        nW1, nb1, nW2, nb2, aW1, ab1, aW2, ab2, oW1, ob1, oW2, ob2,
        out, batch);
}

// round 5
// speedup vs baseline: 1.4492x; 1.3788x over previous
#include <cuda_runtime.h>
#include <cuda_fp16.h>
#include <stdint.h>
#include <math.h>

#define NT   256
#define TILE 128

// weight blob layout: n-major [64 rows][Kpad halves], hi and lo arrays
#define KP64  144                 // bytes per row, K=64  (72 halves)
#define KP128 272                 // bytes per row, K=128 (136 halves)
#define SZ64  (64*KP64)           // 9216
#define SZ128 (64*KP128)          // 17408

#define NW1H 0
#define NW1L (NW1H+SZ64)
#define NW2H (NW1L+SZ64)
#define NW2L (NW2H+SZ64)
#define AW1H (NW2L+SZ64)
#define AW1L (AW1H+SZ128)
#define AW2H (AW1L+SZ128)
#define AW2L (AW2H+SZ64)
#define OW1H (AW2L+SZ64)
#define OW1L (OW1H+SZ128)
#define OW2H (OW1L+SZ128)
#define OW2L (OW2H+SZ64)
#define WBYTES (OW2L+SZ64)        // 143360

#define BIAS_OFF WBYTES
#define TV_OFF   (BIAS_OFF + 6*64*4)
#define SMEM_REQ (TV_OFF + 256)

__device__ __align__(16) unsigned char g_wblob[WBYTES];

// ---------------- helpers ----------------
__device__ __forceinline__ uint32_t smem_u32(const void* p) {
    uint32_t a;
    asm("{ .reg .u64 t; cvta.to.shared.u64 t, %1; cvt.u32.u64 %0, t; }" : "=r"(a) : "l"(p));
    return a;
}

__device__ __forceinline__ void split2(float x0, float x1, uint32_t& hi, uint32_t& lo) {
    __half h0 = __float2half_rn(x0), h1 = __float2half_rn(x1);
    __half l0 = __float2half_rn(x0 - __half2float(h0));
    __half l1 = __float2half_rn(x1 - __half2float(h1));
    __half2 H = __halves2half2(h0, h1), L = __halves2half2(l0, l1);
    hi = *reinterpret_cast<uint32_t*>(&H);
    lo = *reinterpret_cast<uint32_t*>(&L);
}

#define MMA(D, a0, a1, a2, a3, b0, b1) \
    asm volatile("mma.sync.aligned.m16n8k16.row.col.f32.f16.f16.f32 " \
        "{%0,%1,%2,%3},{%4,%5,%6,%7},{%8,%9},{%0,%1,%2,%3};" \
        : "+f"((D)[0]), "+f"((D)[1]), "+f"((D)[2]), "+f"((D)[3]) \
        : "r"(a0), "r"(a1), "r"(a2), "r"(a3), "r"(b0), "r"(b1))

#define LDSM4(r0, r1, r2, r3, a) \
    asm volatile("ldmatrix.sync.aligned.m8n8.x4.shared.b16 {%0,%1,%2,%3}, [%4];" \
        : "=r"(r0), "=r"(r1), "=r"(r2), "=r"(r3) : "r"(a))

struct Slot { uint32_t h[16]; uint32_t l[16]; };

// ---------------- weight conversion (runs once per replay; tiny) ----------------
__global__ void convert_weights(const float* __restrict__ nW1, const float* __restrict__ nW2,
                                const float* __restrict__ aW1, const float* __restrict__ aW2,
                                const float* __restrict__ oW1, const float* __restrict__ oW2) {
    int i = blockIdx.x * blockDim.x + threadIdx.x;
    if (i >= 32768) return;
    int idx = i; const float* src; int hb, lb, kp;
    if (idx < 4096)       { src = nW1; hb = NW1H; lb = NW1L; kp = KP64; }
    else if (idx < 8192)  { idx -= 4096;  src = nW2; hb = NW2H; lb = NW2L; kp = KP64; }
    else if (idx < 16384) { idx -= 8192;  src = aW1; hb = AW1H; lb = AW1L; kp = KP128; }
    else if (idx < 20480) { idx -= 16384; src = aW2; hb = AW2H; lb = AW2L; kp = KP64; }
    else if (idx < 28672) { idx -= 20480; src = oW1; hb = OW1H; lb = OW1L; kp = KP128; }
    else                  { idx -= 28672; src = oW2; hb = OW2H; lb = OW2L; kp = KP64; }
    int k = idx >> 6, n = idx & 63;          // source row-major [K][64]
    float w = src[idx];
    __half h = __float2half_rn(w);
    __half l = __float2half_rn(w - __half2float(h));
    *(__half*)(g_wblob + hb + n * kp + k * 2) = h;
    *(__half*)(g_wblob + lb + n * kp + k * 2) = l;
}

// ---------------- core compute pieces (all per-warp, register resident) ----------------
__device__ __forceinline__ void zeroD(float (&D)[8][4]) {
#pragma unroll
    for (int n = 0; n < 8; n++)
#pragma unroll
        for (int i = 0; i < 4; i++) D[n][i] = 0.f;
}

// accumulate one K=64 chunk: D += Ah*Wh + Ah*Wl + Al*Wh
__device__ __forceinline__ void chunk64(float (&D)[8][4], const Slot& A,
                                        uint32_t baseH, uint32_t baseL, int kpB, int k0,
                                        int bn, int bk) {
#pragma unroll
    for (int kt = 0; kt < 4; kt++) {
        int kbyte = (k0 + kt * 16 + bk) * 2;
#pragma unroll
        for (int np = 0; np < 4; np++) {
            uint32_t rowoff = (uint32_t)((np * 16 + bn) * kpB + kbyte);
            uint32_t h0, h1, h2, h3, l0, l1, l2, l3;
            LDSM4(h0, h1, h2, h3, baseH + rowoff);
            LDSM4(l0, l1, l2, l3, baseL + rowoff);
            MMA(D[2*np],   A.h[kt*4], A.h[kt*4+1], A.h[kt*4+2], A.h[kt*4+3], h0, h1);
            MMA(D[2*np+1], A.h[kt*4], A.h[kt*4+1], A.h[kt*4+2], A.h[kt*4+3], h2, h3);
            MMA(D[2*np],   A.h[kt*4], A.h[kt*4+1], A.h[kt*4+2], A.h[kt*4+3], l0, l1);
            MMA(D[2*np+1], A.h[kt*4], A.h[kt*4+1], A.h[kt*4+2], A.h[kt*4+3], l2, l3);
            MMA(D[2*np],   A.l[kt*4], A.l[kt*4+1], A.l[kt*4+2], A.l[kt*4+3], h0, h1);
            MMA(D[2*np+1], A.l[kt*4], A.l[kt*4+1], A.l[kt*4+2], A.l[kt*4+3], h2, h3);
        }
    }
}

// D + bias (+lrelu) -> split fp16 hi/lo into slot (A-fragment layout for next layer)
__device__ __forceinline__ void epi_slot(float (&D)[8][4], const float* __restrict__ bias,
                                         bool lrelu, Slot& S, int lane) {
    int c0 = 2 * (lane & 3);
#pragma unroll
    for (int nt = 0; nt < 8; nt++) {
        float b0 = bias[nt*8 + c0], b1 = bias[nt*8 + c0 + 1];
        float x0 = D[nt][0] + b0, x1 = D[nt][1] + b1;
        float x2 = D[nt][2] + b0, x3 = D[nt][3] + b1;
        if (lrelu) {
            x0 = x0 > 0.f ? x0 : 0.01f * x0;
            x1 = x1 > 0.f ? x1 : 0.01f * x1;
            x2 = x2 > 0.f ? x2 : 0.01f * x2;
            x3 = x3 > 0.f ? x3 : 0.01f * x3;
        }
        int r = (nt >> 1) * 4 + (nt & 1) * 2;
        split2(x0, x1, S.h[r],     S.l[r]);
        split2(x2, x3, S.h[r + 1], S.l[r + 1]);
    }
}

// two-layer MLP: leaves layer-2 raw accumulators in D (bias NOT yet applied)
__device__ __forceinline__ void mlp(float (&D)[8][4], Slot& H,
                                    const Slot& in1, const Slot* in2, uint32_t sb,
                                    uint32_t w1h, uint32_t w1l, int kp1, const float* b1,
                                    uint32_t w2h, uint32_t w2l,
                                    int bn, int bk, int lane) {
    zeroD(D);
    chunk64(D, in1, sb + w1h, sb + w1l, kp1, 0, bn, bk);
    if (in2) chunk64(D, *in2, sb + w1h, sb + w1l, kp1, 64, bn, bk);
    epi_slot(D, b1, true, H, lane);
    zeroD(D);
    chunk64(D, H, sb + w2h, sb + w2l, KP64, 0, bn, bk);
}

// gather embedding rows (r1, r2 = r1+8) directly into A-fragment registers
__device__ __forceinline__ void gather(Slot& S, const float* __restrict__ item,
                                       int i1, int i2, int lane) {
    const float* p1 = item + (size_t)i1 * 64 + 2 * (lane & 3);
    const float* p2 = item + (size_t)i2 * 64 + 2 * (lane & 3);
#pragma unroll
    for (int j = 0; j < 4; j++) {
        float2 a = *(const float2*)(p1 + j * 16);
        float2 b = *(const float2*)(p2 + j * 16);
        float2 c = *(const float2*)(p1 + j * 16 + 8);
        float2 d = *(const float2*)(p2 + j * 16 + 8);
        split2(a.x, a.y, S.h[j*4+0], S.l[j*4+0]);
        split2(b.x, b.y, S.h[j*4+1], S.l[j*4+1]);
        split2(c.x, c.y, S.h[j*4+2], S.l[j*4+2]);
        split2(d.x, d.y, S.h[j*4+3], S.l[j*4+3]);
    }
}

// cosine-similarity epilogue on raw layer-2 accumulators
__device__ __forceinline__ void final_epi(float (&D)[8][4], const float* __restrict__ bias,
                                          const float* __restrict__ tv, float tnorm,
                                          float* __restrict__ outp, int r1, int lane) {
    int c0 = 2 * (lane & 3);
    float n1 = 0.f, s1 = 0.f, n2 = 0.f, s2 = 0.f;
#pragma unroll
    for (int nt = 0; nt < 8; nt++) {
        float b0 = bias[nt*8 + c0], b1 = bias[nt*8 + c0 + 1];
        float t0 = tv[nt*8 + c0],  t1 = tv[nt*8 + c0 + 1];
        float x0 = D[nt][0] + b0, x1 = D[nt][1] + b1;
        float x2 = D[nt][2] + b0, x3 = D[nt][3] + b1;
        n1 = fmaf(x0, t0, fmaf(x1, t1, n1));  s1 = fmaf(x0, x0, fmaf(x1, x1, s1));
        n2 = fmaf(x2, t0, fmaf(x3, t1, n2));  s2 = fmaf(x2, x2, fmaf(x3, x3, s2));
    }
    n1 += __shfl_xor_sync(~0u, n1, 1); n1 += __shfl_xor_sync(~0u, n1, 2);
    s1 += __shfl_xor_sync(~0u, s1, 1); s1 += __shfl_xor_sync(~0u, s1, 2);
    n2 += __shfl_xor_sync(~0u, n2, 1); n2 += __shfl_xor_sync(~0u, n2, 2);
    s2 += __shfl_xor_sync(~0u, s2, 1); s2 += __shfl_xor_sync(~0u, s2, 2);
    if ((lane & 3) == 0) {
        float dn = fmaxf(tnorm, 1e-8f);
        outp[r1]     = n1 / (fmaxf(sqrtf(s1), 1e-8f) * dn) * 10.0f;
        outp[r1 + 8] = n2 / (fmaxf(sqrtf(s2), 1e-8f) * dn) * 10.0f;
    }
}

// ---------------- main kernel ----------------
__global__ void __launch_bounds__(NT, 1) logicnet_mma(
    const int* __restrict__ seq, const int* __restrict__ post, const int* __restrict__ negt,
    const float* __restrict__ item, const float* __restrict__ tvec,
    const float* __restrict__ nb1, const float* __restrict__ nb2,
    const float* __restrict__ ab1, const float* __restrict__ ab2,
    const float* __restrict__ ob1, const float* __restrict__ ob2,
    float* __restrict__ out, int batch)
{
    extern __shared__ unsigned char sm[];
    {   // stage pre-split, pre-laid-out weights
        const float4* s4 = (const float4*)g_wblob;
        float4* d4 = (float4*)sm;
        for (int i = threadIdx.x; i < WBYTES / 16; i += NT) d4[i] = s4[i];
    }
    float* bias = (float*)(sm + BIAS_OFF);
    if (threadIdx.x < 64) {
        int t = threadIdx.x;
        bias[t]       = nb1[t]; bias[64 + t]  = nb2[t];
        bias[128 + t] = ab1[t]; bias[192 + t] = ab2[t];
        bias[256 + t] = ob1[t]; bias[320 + t] = ob2[t];
        ((float*)(sm + TV_OFF))[t] = tvec[t];
    }
    __syncthreads();

    const uint32_t sb = smem_u32(sm);
    const float* tv = (const float*)(sm + TV_OFF);
    const int lane = threadIdx.x & 31;
    const int wid  = threadIdx.x >> 5;
    const int bn = (lane & 7) + ((lane >> 4) << 3);   // ldmatrix row-lane -> n offset
    const int bk = ((lane >> 3) & 1) * 8;             // ldmatrix row-lane -> k offset
    const int r1 = blockIdx.x * TILE + wid * 16 + (lane >> 2);
    const int r2 = r1 + 8;

    float tn = tv[lane] * tv[lane] + tv[lane + 32] * tv[lane + 32];
#pragma unroll
    for (int m = 16; m; m >>= 1) tn += __shfl_xor_sync(~0u, tn, m);
    const float tnorm = sqrtf(tn);

    Slot S0, S1, S2, H;
    float D[8][4];

    gather(S0, item, seq[r1 * 5 + 0], seq[r2 * 5 + 0], lane);      // e0
    gather(S1, item, seq[r1 * 5 + 1], seq[r2 * 5 + 1], lane);      // e1
    // n1 = NOT(e1) -> S1
    mlp(D, H, S1, nullptr, sb, NW1H, NW1L, KP64,  bias + 0,   NW2H, NW2L, bn, bk, lane);
    epi_slot(D, bias + 64, false, S1, lane);
    // i5 = AND(e0, n1) -> S0
    mlp(D, H, S0, &S1,     sb, AW1H, AW1L, KP128, bias + 128, AW2H, AW2L, bn, bk, lane);
    epi_slot(D, bias + 192, false, S0, lane);
    gather(S1, item, seq[r1 * 5 + 2], seq[r2 * 5 + 2], lane);      // e2
    gather(S2, item, seq[r1 * 5 + 3], seq[r2 * 5 + 3], lane);      // e3
    // i6 = OR(e2, e3) -> S1
    mlp(D, H, S1, &S2,     sb, OW1H, OW1L, KP128, bias + 256, OW2H, OW2L, bn, bk, lane);
    epi_slot(D, bias + 320, false, S1, lane);
    // i7 = AND(i5, i6) -> S0
    mlp(D, H, S0, &S1,     sb, AW1H, AW1L, KP128, bias + 128, AW2H, AW2L, bn, bk, lane);
    epi_slot(D, bias + 192, false, S0, lane);
    // n7 = NOT(i7) -> S1
    mlp(D, H, S0, nullptr, sb, NW1H, NW1L, KP64,  bias + 0,   NW2H, NW2L, bn, bk, lane);
    epi_slot(D, bias + 64, false, S1, lane);
    gather(S2, item, seq[r1 * 5 + 4], seq[r2 * 5 + 4], lane);      // e4
    // i8 = OR(n7, e4) -> S0
    mlp(D, H, S1, &S2,     sb, OW1H, OW1L, KP128, bias + 256, OW2H, OW2L, bn, bk, lane);
    epi_slot(D, bias + 320, false, S0, lane);
    // enc_not = NOT(i8) -> S1
    mlp(D, H, S0, nullptr, sb, NW1H, NW1L, KP64,  bias + 0,   NW2H, NW2L, bn, bk, lane);
    epi_slot(D, bias + 64, false, S1, lane);
    gather(S2, item, post[r1], post[r2], lane);                    // pos_e
    // encoded_pos = OR(enc_not, pos_e) -> out[0:batch]
    mlp(D, H, S1, &S2,     sb, OW1H, OW1L, KP128, bias + 256, OW2H, OW2L, bn, bk, lane);
    final_epi(D, bias + 320, tv, tnorm, out, r1, lane);
    gather(S2, item, negt[r1], negt[r2], lane);                    // neg_e
    // encoded_neg = OR(enc_not, neg_e) -> out[batch:2*batch]
    mlp(D, H, S1, &S2,     sb, OW1H, OW1L, KP128, bias + 256, OW2H, OW2L, bn, bk, lane);
    final_epi(D, bias + 320, tv, tnorm, out + batch, r1, lane);
}

extern "C" void kernel_launch(void* const* d_in, const int* in_sizes, int n_in,
                              void* d_out, int out_size) {
    const int*   seq   = (const int*)  d_in[0];
    const int*   pos_t = (const int*)  d_in[1];
    const int*   neg_t = (const int*)  d_in[2];
    const float* item  = (const float*)d_in[3];
    const float* tvec  = (const float*)d_in[4];
    const float* nW1 = (const float*)d_in[5];
    const float* nb1 = (const float*)d_in[6];
    const float* nW2 = (const float*)d_in[7];
    const float* nb2 = (const float*)d_in[8];
    const float* aW1 = (const float*)d_in[9];
    const float* ab1 = (const float*)d_in[10];
    const float* aW2 = (const float*)d_in[11];
    const float* ab2 = (const float*)d_in[12];
    const float* oW1 = (const float*)d_in[13];
    const float* ob1 = (const float*)d_in[14];
    const float* oW2 = (const float*)d_in[15];
    const float* ob2 = (const float*)d_in[16];
    float* out = (float*)d_out;

    int batch = in_sizes[1];
    convert_weights<<<128, 256>>>(nW1, nW2, aW1, aW2, oW1, oW2);

    cudaFuncSetAttribute(logicnet_mma, cudaFuncAttributeMaxDynamicSharedMemorySize, SMEM_REQ);
    logicnet_mma<<<batch / TILE, NT, SMEM_REQ>>>(
        seq, pos_t, neg_t, item, tvec,
        nb1, nb2, ab1, ab2, ob1, ob2, out, batch);
}

// round 6
// speedup vs baseline: 3.9489x; 2.7248x over previous
#include <cuda_runtime.h>
#include <cuda_fp16.h>
#include <stdint.h>
#include <math.h>

#define NT   256
#define TILE 128

// weight blob layout: n-major [64 rows][Kpad halves], hi and lo arrays
#define KP64  144                 // bytes per row, K=64  (72 halves)
#define KP128 272                 // bytes per row, K=128 (136 halves)
#define SZ64  (64*KP64)           // 9216
#define SZ128 (64*KP128)          // 17408

#define NW1H 0
#define NW1L (NW1H+SZ64)
#define NW2H (NW1L+SZ64)
#define NW2L (NW2H+SZ64)
#define AW1H (NW2L+SZ64)
#define AW1L (AW1H+SZ128)
#define AW2H (AW1L+SZ128)
#define AW2L (AW2H+SZ64)
#define OW1H (AW2L+SZ64)
#define OW1L (OW1H+SZ128)
#define OW2H (OW1L+SZ128)
#define OW2L (OW2H+SZ64)
#define WBYTES (OW2L+SZ64)        // 143360

#define BIAS_OFF WBYTES           // 1536 B
#define TV_OFF   (BIAS_OFF + 1536)
#define ACT_OFF  (TV_OFF + 256)   // 145152
// activation lo buffers: 128 rows x 144 B, 4 buffers (S0,S1,S2,H)
#define ABUF     18432
#define SMEM_REQ (ACT_OFF + 4*ABUF)   // 218880

__device__ __align__(16) unsigned char g_wblob[WBYTES];

// ---------------- helpers ----------------
__device__ __forceinline__ uint32_t smem_u32(const void* p) {
    uint32_t a;
    asm("{ .reg .u64 t; cvta.to.shared.u64 t, %1; cvt.u32.u64 %0, t; }" : "=r"(a) : "l"(p));
    return a;
}

__device__ __forceinline__ void split2(float x0, float x1, uint32_t& hi, uint32_t& lo) {
    __half h0 = __float2half_rn(x0), h1 = __float2half_rn(x1);
    __half l0 = __float2half_rn(x0 - __half2float(h0));
    __half l1 = __float2half_rn(x1 - __half2float(h1));
    __half2 H = __halves2half2(h0, h1), L = __halves2half2(l0, l1);
    hi = *reinterpret_cast<uint32_t*>(&H);
    lo = *reinterpret_cast<uint32_t*>(&L);
}

#define MMA(D, a0, a1, a2, a3, b0, b1) \
    asm volatile("mma.sync.aligned.m16n8k16.row.col.f32.f16.f16.f32 " \
        "{%0,%1,%2,%3},{%4,%5,%6,%7},{%8,%9},{%0,%1,%2,%3};" \
        : "+f"((D)[0]), "+f"((D)[1]), "+f"((D)[2]), "+f"((D)[3]) \
        : "r"(a0), "r"(a1), "r"(a2), "r"(a3), "r"(b0), "r"(b1))

#define LDSM4(r0, r1, r2, r3, a) \
    asm volatile("ldmatrix.sync.aligned.m8n8.x4.shared.b16 {%0,%1,%2,%3}, [%4];" \
        : "=r"(r0), "=r"(r1), "=r"(r2), "=r"(r3) : "r"(a))

#define STS32(a, v) asm volatile("st.shared.b32 [%0], %1;" :: "r"(a), "r"(v) : "memory")

struct Slot { uint32_t h[16]; };   // activation hi halves only (lo lives in smem)

// ---------------- weight conversion ----------------
__global__ void convert_weights(const float* __restrict__ nW1, const float* __restrict__ nW2,
                                const float* __restrict__ aW1, const float* __restrict__ aW2,
                                const float* __restrict__ oW1, const float* __restrict__ oW2) {
    int i = blockIdx.x * blockDim.x + threadIdx.x;
    if (i >= 32768) return;
    int idx = i; const float* src; int hb, lb, kp;
    if (idx < 4096)       { src = nW1; hb = NW1H; lb = NW1L; kp = KP64; }
    else if (idx < 8192)  { idx -= 4096;  src = nW2; hb = NW2H; lb = NW2L; kp = KP64; }
    else if (idx < 16384) { idx -= 8192;  src = aW1; hb = AW1H; lb = AW1L; kp = KP128; }
    else if (idx < 20480) { idx -= 16384; src = aW2; hb = AW2H; lb = AW2L; kp = KP64; }
    else if (idx < 28672) { idx -= 20480; src = oW1; hb = OW1H; lb = OW1L; kp = KP128; }
    else                  { idx -= 28672; src = oW2; hb = OW2H; lb = OW2L; kp = KP64; }
    int k = idx >> 6, n = idx & 63;
    float w = src[idx];
    __half h = __float2half_rn(w);
    __half l = __float2half_rn(w - __half2float(h));
    *(__half*)(g_wblob + hb + n * kp + k * 2) = h;
    *(__half*)(g_wblob + lb + n * kp + k * 2) = l;
}

// ---------------- core compute ----------------
__device__ __forceinline__ void zeroD(float (&D)[8][4]) {
#pragma unroll
    for (int n = 0; n < 8; n++)
#pragma unroll
        for (int i = 0; i < 4; i++) D[n][i] = 0.f;
}

// one K=64 chunk: D += Ah*Wh + Ah*Wl + Al*Wh   (Al via ldmatrix from smem)
__device__ __forceinline__ void chunk64(float (&D)[8][4], const Slot& A, uint32_t alo,
                                        uint32_t baseH, uint32_t baseL, int kpB, int k0,
                                        int bn, int bk) {
#pragma unroll
    for (int kt = 0; kt < 4; kt++) {
        int kbyte = (k0 + kt * 16 + bk) * 2;
        uint32_t al0, al1, al2, al3;
        LDSM4(al0, al1, al2, al3, alo + (uint32_t)((kt * 16) * 2));
#pragma unroll
        for (int np = 0; np < 4; np++) {
            uint32_t rowoff = (uint32_t)((np * 16 + bn) * kpB + kbyte);
            uint32_t h0, h1, h2, h3, l0, l1, l2, l3;
            LDSM4(h0, h1, h2, h3, baseH + rowoff);
            LDSM4(l0, l1, l2, l3, baseL + rowoff);
            MMA(D[2*np],   A.h[kt*4], A.h[kt*4+1], A.h[kt*4+2], A.h[kt*4+3], h0, h1);
            MMA(D[2*np+1], A.h[kt*4], A.h[kt*4+1], A.h[kt*4+2], A.h[kt*4+3], h2, h3);
            MMA(D[2*np],   A.h[kt*4], A.h[kt*4+1], A.h[kt*4+2], A.h[kt*4+3], l0, l1);
            MMA(D[2*np+1], A.h[kt*4], A.h[kt*4+1], A.h[kt*4+2], A.h[kt*4+3], l2, l3);
            MMA(D[2*np],   al0, al1, al2, al3, h0, h1);
            MMA(D[2*np+1], al0, al1, al2, al3, h2, h3);
        }
    }
}

// D + bias (+lrelu) -> hi into regs (A-frag layout), lo into smem buffer
__device__ __forceinline__ void epi_slot(float (&D)[8][4], const float* __restrict__ bias,
                                         bool lrelu, Slot& S, uint32_t loW, int lane) {
    int c0 = 2 * (lane & 3);
#pragma unroll
    for (int nt = 0; nt < 8; nt++) {
        float b0 = bias[nt*8 + c0], b1 = bias[nt*8 + c0 + 1];
        float x0 = D[nt][0] + b0, x1 = D[nt][1] + b1;
        float x2 = D[nt][2] + b0, x3 = D[nt][3] + b1;
        if (lrelu) {
            x0 = x0 > 0.f ? x0 : 0.01f * x0;
            x1 = x1 > 0.f ? x1 : 0.01f * x1;
            x2 = x2 > 0.f ? x2 : 0.01f * x2;
            x3 = x3 > 0.f ? x3 : 0.01f * x3;
        }
        int r = (nt >> 1) * 4 + (nt & 1) * 2;
        uint32_t lo01, lo23;
        split2(x0, x1, S.h[r],     lo01);
        split2(x2, x3, S.h[r + 1], lo23);
        STS32(loW + (uint32_t)(nt * 16),        lo01);   // row g,   col nt*8+c0
        STS32(loW + (uint32_t)(nt * 16 + 1152), lo23);   // row g+8
    }
    __syncwarp();
}

// two-layer MLP: leaves layer-2 raw accumulators in D (bias not applied)
__device__ __forceinline__ void mlp(float (&D)[8][4], Slot& H,
                                    const Slot& in1, const Slot* in2,
                                    uint32_t alo1, uint32_t alo2,
                                    uint32_t aloH, uint32_t loWH, uint32_t sb,
                                    uint32_t w1h, uint32_t w1l, int kp1, const float* b1,
                                    uint32_t w2h, uint32_t w2l,
                                    int bn, int bk, int lane) {
    zeroD(D);
    chunk64(D, in1, alo1, sb + w1h, sb + w1l, kp1, 0, bn, bk);
    if (in2) chunk64(D, *in2, alo2, sb + w1h, sb + w1l, kp1, 64, bn, bk);
    epi_slot(D, b1, true, H, loWH, lane);
    zeroD(D);
    chunk64(D, H, aloH, sb + w2h, sb + w2l, KP64, 0, bn, bk);
}

// gather embedding rows (r1, r2 = r1+8): hi into regs, lo into smem buffer
__device__ __forceinline__ void gather(Slot& S, uint32_t loW, const float* __restrict__ item,
                                       int i1, int i2, int lane) {
    const float* p1 = item + (size_t)i1 * 64 + 2 * (lane & 3);
    const float* p2 = item + (size_t)i2 * 64 + 2 * (lane & 3);
#pragma unroll
    for (int j = 0; j < 4; j++) {
        float2 a = *(const float2*)(p1 + j * 16);
        float2 b = *(const float2*)(p2 + j * 16);
        float2 c = *(const float2*)(p1 + j * 16 + 8);
        float2 d = *(const float2*)(p2 + j * 16 + 8);
        uint32_t lo;
        split2(a.x, a.y, S.h[j*4+0], lo); STS32(loW + (uint32_t)(j*32),            lo);
        split2(b.x, b.y, S.h[j*4+1], lo); STS32(loW + (uint32_t)(j*32 + 1152),     lo);
        split2(c.x, c.y, S.h[j*4+2], lo); STS32(loW + (uint32_t)(j*32 + 16),       lo);
        split2(d.x, d.y, S.h[j*4+3], lo); STS32(loW + (uint32_t)(j*32 + 1152+16),  lo);
    }
    __syncwarp();
}

// cosine-similarity epilogue on raw layer-2 accumulators
__device__ __forceinline__ void final_epi(float (&D)[8][4], const float* __restrict__ bias,
                                          const float* __restrict__ tv, float tnorm,
                                          float* __restrict__ outp, int r1, int lane) {
    int c0 = 2 * (lane & 3);
    float n1 = 0.f, s1 = 0.f, n2 = 0.f, s2 = 0.f;
#pragma unroll
    for (int nt = 0; nt < 8; nt++) {
        float b0 = bias[nt*8 + c0], b1 = bias[nt*8 + c0 + 1];
        float t0 = tv[nt*8 + c0],  t1 = tv[nt*8 + c0 + 1];
        float x0 = D[nt][0] + b0, x1 = D[nt][1] + b1;
        float x2 = D[nt][2] + b0, x3 = D[nt][3] + b1;
        n1 = fmaf(x0, t0, fmaf(x1, t1, n1));  s1 = fmaf(x0, x0, fmaf(x1, x1, s1));
        n2 = fmaf(x2, t0, fmaf(x3, t1, n2));  s2 = fmaf(x2, x2, fmaf(x3, x3, s2));
    }
    n1 += __shfl_xor_sync(~0u, n1, 1); n1 += __shfl_xor_sync(~0u, n1, 2);
    s1 += __shfl_xor_sync(~0u, s1, 1); s1 += __shfl_xor_sync(~0u, s1, 2);
    n2 += __shfl_xor_sync(~0u, n2, 1); n2 += __shfl_xor_sync(~0u, n2, 2);
    s2 += __shfl_xor_sync(~0u, s2, 1); s2 += __shfl_xor_sync(~0u, s2, 2);
    if ((lane & 3) == 0) {
        float dn = fmaxf(tnorm, 1e-8f);
        outp[r1]     = n1 / (fmaxf(sqrtf(s1), 1e-8f) * dn) * 10.0f;
        outp[r1 + 8] = n2 / (fmaxf(sqrtf(s2), 1e-8f) * dn) * 10.0f;
    }
}

// ---------------- main kernel ----------------
__global__ void __launch_bounds__(NT, 1) logicnet_mma(
    const int* __restrict__ seq, const int* __restrict__ post, const int* __restrict__ negt,
    const float* __restrict__ item, const float* __restrict__ tvec,
    const float* __restrict__ nb1, const float* __restrict__ nb2,
    const float* __restrict__ ab1, const float* __restrict__ ab2,
    const float* __restrict__ ob1, const float* __restrict__ ob2,
    float* __restrict__ out, int batch)
{
    extern __shared__ unsigned char sm[];
    {   // stage pre-split, pre-laid-out weights
        const float4* s4 = (const float4*)g_wblob;
        float4* d4 = (float4*)sm;
        for (int i = threadIdx.x; i < WBYTES / 16; i += NT) d4[i] = s4[i];
    }
    float* bias = (float*)(sm + BIAS_OFF);
    if (threadIdx.x < 64) {
        int t = threadIdx.x;
        bias[t]       = nb1[t]; bias[64 + t]  = nb2[t];
        bias[128 + t] = ab1[t]; bias[192 + t] = ab2[t];
        bias[256 + t] = ob1[t]; bias[320 + t] = ob2[t];
        ((float*)(sm + TV_OFF))[t] = tvec[t];
    }
    __syncthreads();

    const uint32_t sb = smem_u32(sm);
    const float* tv = (const float*)(sm + TV_OFF);
    const int lane = threadIdx.x & 31;
    const int wid  = threadIdx.x >> 5;
    const int bn = (lane & 7) + ((lane >> 4) << 3);
    const int bk = ((lane >> 3) & 1) * 8;
    const int r1 = blockIdx.x * TILE + wid * 16 + (lane >> 2);
    const int r2 = r1 + 8;

    // per-thread activation-lo smem addressing (warp-private 16 rows, 144B stride)
    const uint32_t actRd = sb + ACT_OFF + (uint32_t)((wid*16 + (lane & 15)) * 144 + ((lane >> 4) << 4));
    const uint32_t actWr = sb + ACT_OFF + (uint32_t)((wid*16 + (lane >> 2)) * 144 + ((lane & 3) << 2));
    const uint32_t aloS0 = actRd,            aloS1 = actRd + ABUF;
    const uint32_t aloS2 = actRd + 2*ABUF,   aloH  = actRd + 3*ABUF;
    const uint32_t loWS0 = actWr,            loWS1 = actWr + ABUF;
    const uint32_t loWS2 = actWr + 2*ABUF,   loWH  = actWr + 3*ABUF;

    float tn = tv[lane] * tv[lane] + tv[lane + 32] * tv[lane + 32];
#pragma unroll
    for (int m = 16; m; m >>= 1) tn += __shfl_xor_sync(~0u, tn, m);
    const float tnorm = sqrtf(tn);

    Slot S0, S1, S2, H;
    float D[8][4];

    gather(S0, loWS0, item, seq[r1 * 5 + 0], seq[r2 * 5 + 0], lane);   // e0
    gather(S1, loWS1, item, seq[r1 * 5 + 1], seq[r2 * 5 + 1], lane);   // e1
    // n1 = NOT(e1) -> S1
    mlp(D, H, S1, nullptr, aloS1, 0,     aloH, loWH, sb, NW1H, NW1L, KP64,  bias + 0,   NW2H, NW2L, bn, bk, lane);
    epi_slot(D, bias + 64, false, S1, loWS1, lane);
    // i5 = AND(e0, n1) -> S0
    mlp(D, H, S0, &S1,     aloS0, aloS1, aloH, loWH, sb, AW1H, AW1L, KP128, bias + 128, AW2H, AW2L, bn, bk, lane);
    epi_slot(D, bias + 192, false, S0, loWS0, lane);
    gather(S1, loWS1, item, seq[r1 * 5 + 2], seq[r2 * 5 + 2], lane);   // e2
    gather(S2, loWS2, item, seq[r1 * 5 + 3], seq[r2 * 5 + 3], lane);   // e3
    // i6 = OR(e2, e3) -> S1
    mlp(D, H, S1, &S2,     aloS1, aloS2, aloH, loWH, sb, OW1H, OW1L, KP128, bias + 256, OW2H, OW2L, bn, bk, lane);
    epi_slot(D, bias + 320, false, S1, loWS1, lane);
    // i7 = AND(i5, i6) -> S0
    mlp(D, H, S0, &S1,     aloS0, aloS1, aloH, loWH, sb, AW1H, AW1L, KP128, bias + 128, AW2H, AW2L, bn, bk, lane);
    epi_slot(D, bias + 192, false, S0, loWS0, lane);
    // n7 = NOT(i7) -> S1
    mlp(D, H, S0, nullptr, aloS0, 0,     aloH, loWH, sb, NW1H, NW1L, KP64,  bias + 0,   NW2H, NW2L, bn, bk, lane);
    epi_slot(D, bias + 64, false, S1, loWS1, lane);
    gather(S2, loWS2, item, seq[r1 * 5 + 4], seq[r2 * 5 + 4], lane);   // e4
    // i8 = OR(n7, e4) -> S0
    mlp(D, H, S1, &S2,     aloS1, aloS2, aloH, loWH, sb, OW1H, OW1L, KP128, bias + 256, OW2H, OW2L, bn, bk, lane);
    epi_slot(D, bias + 320, false, S0, loWS0, lane);
    // enc_not = NOT(i8) -> S1
    mlp(D, H, S0, nullptr, aloS0, 0,     aloH, loWH, sb, NW1H, NW1L, KP64,  bias + 0,   NW2H, NW2L, bn, bk, lane);
    epi_slot(D, bias + 64, false, S1, loWS1, lane);
    gather(S2, loWS2, item, post[r1], post[r2], lane);                 // pos_e
    // encoded_pos = OR(enc_not, pos_e)
    mlp(D, H, S1, &S2,     aloS1, aloS2, aloH, loWH, sb, OW1H, OW1L, KP128, bias + 256, OW2H, OW2L, bn, bk, lane);
    final_epi(D, bias + 320, tv, tnorm, out, r1, lane);
    gather(S2, loWS2, item, negt[r1], negt[r2], lane);                 // neg_e
    // encoded_neg = OR(enc_not, neg_e)
    mlp(D, H, S1, &S2,     aloS1, aloS2, aloH, loWH, sb, OW1H, OW1L, KP128, bias + 256, OW2H, OW2L, bn, bk, lane);
    final_epi(D, bias + 320, tv, tnorm, out + batch, r1, lane);
}

extern "C" void kernel_launch(void* const* d_in, const int* in_sizes, int n_in,
                              void* d_out, int out_size) {
    const int*   seq   = (const int*)  d_in[0];
    const int*   pos_t = (const int*)  d_in[1];
    const int*   neg_t = (const int*)  d_in[2];
    const float* item  = (const float*)d_in[3];
    const float* tvec  = (const float*)d_in[4];
    const float* nW1 = (const float*)d_in[5];
    const float* nb1 = (const float*)d_in[6];
    const float* nW2 = (const float*)d_in[7];
    const float* nb2 = (const float*)d_in[8];
    const float* aW1 = (const float*)d_in[9];
    const float* ab1 = (const float*)d_in[10];
    const float* aW2 = (const float*)d_in[11];
    const float* ab2 = (const float*)d_in[12];
    const float* oW1 = (const float*)d_in[13];
    const float* ob1 = (const float*)d_in[14];
    const float* oW2 = (const float*)d_in[15];
    const float* ob2 = (const float*)d_in[16];
    float* out = (float*)d_out;

    int batch = in_sizes[1];
    convert_weights<<<128, 256>>>(nW1, nW2, aW1, aW2, oW1, oW2);

    cudaFuncSetAttribute(logicnet_mma, cudaFuncAttributeMaxDynamicSharedMemorySize, SMEM_REQ);
    logicnet_mma<<<batch / TILE, NT, SMEM_REQ>>>(
        seq, pos_t, neg_t, item, tvec,
        nb1, nb2, ab1, ab2, ob1, ob2, out, batch);
}